// round 7
// baseline (speedup 1.0000x reference)
#include <cuda_runtime.h>
#include <cuda_bf16.h>
#include <stdint.h>

// Problem dims
#define NROW   16384      // B*S
#define OBSD   256
#define ACTD   32
#define CIN    288        // OBS+ACT = LAT+ACT
#define HID    2048
#define LATD   256
#define KCODE  4096

// Output layout (float32, tuple flattened in order)
#define OUT_RECON   0
#define OUT_TOK     (NROW*OBSD)
#define OUT_Q       (OUT_TOK + NROW)
#define OUT_LAT     (OUT_Q + NROW*LATD)
#define OUT_SCAL    (OUT_LAT + NROW*LATD)

// Scratch layout (floats)
#define OFF_H1      0
#define SZ_H        (NROW*HID)
#define OFF_H2      (OFF_H1 + SZ_H)
#define OFF_EMBT    (OFF_H2 + SZ_H)
#define SZ_EMBT     (LATD*KCODE)
#define OFF_ECN     (OFF_EMBT + SZ_EMBT)
#define OFF_XN      (OFF_ECN + KCODE)
#define OFF_ARGMIN  (OFF_XN + NROW)
#define OFF_ACC     (OFF_ARGMIN + 2*NROW)
#define SCRATCH_SZ  (OFF_ACC + 8)

__device__ __align__(16) float g_scratch[SCRATCH_SZ];

// ---------------------------------------------------------------------------
// helpers
// ---------------------------------------------------------------------------
__device__ __forceinline__ unsigned sortkey(float f) {
    unsigned u = __float_as_uint(f);
    return (u & 0x80000000u) ? ~u : (u | 0x80000000u);
}

__device__ __forceinline__ float block_reduce_sum(float v) {
    #pragma unroll
    for (int o = 16; o > 0; o >>= 1) v += __shfl_xor_sync(0xffffffffu, v, o);
    __shared__ float sh[32];
    int lane = threadIdx.x & 31, w = threadIdx.x >> 5;
    if (lane == 0) sh[w] = v;
    __syncthreads();
    int nw = (blockDim.x + 31) >> 5;
    v = (threadIdx.x < (unsigned)nw) ? sh[threadIdx.x] : 0.0f;
    if (w == 0) {
        #pragma unroll
        for (int o = 16; o > 0; o >>= 1) v += __shfl_xor_sync(0xffffffffu, v, o);
    }
    return v;  // valid on thread 0
}

// ---------------------------------------------------------------------------
// init: reset argmin + loss accumulators (runs at start of every graph replay)
// ---------------------------------------------------------------------------
__global__ void init_kernel(unsigned long long* __restrict__ amin,
                            double* __restrict__ acc) {
    int i = blockIdx.x * blockDim.x + threadIdx.x;
    if (i < NROW) amin[i] = ~0ULL;
    if (i == 0) { acc[0] = 0.0; acc[1] = 0.0; }
}

// ---------------------------------------------------------------------------
// codebook row norms |e_j|^2  (one warp per code)
// ---------------------------------------------------------------------------
__global__ void ecn_kernel(const float* __restrict__ emb, float* __restrict__ ecn) {
    int code = blockIdx.x * 8 + (threadIdx.x >> 5);
    int lane = threadIdx.x & 31;
    const float* row = emb + (size_t)code * LATD;
    float s = 0.f;
    #pragma unroll
    for (int i = 0; i < LATD / 32; i++) {
        float v = row[lane + 32 * i];
        s = fmaf(v, v, s);
    }
    #pragma unroll
    for (int o = 16; o > 0; o >>= 1) s += __shfl_xor_sync(0xffffffffu, s, o);
    if (lane == 0) ecn[code] = s;
}

// ---------------------------------------------------------------------------
// latent row norms |x_r|^2  (one warp per row)
// ---------------------------------------------------------------------------
__global__ void row_norms(const float* __restrict__ lat, float* __restrict__ xn) {
    int row = blockIdx.x * 8 + (threadIdx.x >> 5);
    int lane = threadIdx.x & 31;
    const float* r = lat + (size_t)row * LATD;
    float s = 0.f;
    #pragma unroll
    for (int i = 0; i < LATD / 32; i++) {
        float v = r[lane + 32 * i];
        s = fmaf(v, v, s);
    }
    #pragma unroll
    for (int o = 16; o > 0; o >>= 1) s += __shfl_xor_sync(0xffffffffu, s, o);
    if (lane == 0) xn[row] = s;
}

// ---------------------------------------------------------------------------
// transpose emb [KCODE,LATD] -> embT [LATD,KCODE]
// ---------------------------------------------------------------------------
__global__ void transpose_emb(const float* __restrict__ emb, float* __restrict__ embT) {
    __shared__ float t[32][33];
    int j0 = blockIdx.x * 32;   // code dim
    int k0 = blockIdx.y * 32;   // latent dim
    t[threadIdx.y][threadIdx.x] = emb[(size_t)(j0 + threadIdx.y) * LATD + k0 + threadIdx.x];
    __syncthreads();
    embT[(size_t)(k0 + threadIdx.y) * KCODE + j0 + threadIdx.x] = t[threadIdx.x][threadIdx.y];
}

// ---------------------------------------------------------------------------
// 128x128x16 fp32 SIMT GEMM, 256 threads, 8x8 per thread, 2 CTAs/SM.
// K, N compile-time. Double-buffered smem, one __syncthreads per k-iter.
// Conflict-free fragment layout: rows {ty*4..+3, 64+ty*4..+3},
// cols {tx*4..+3, 64+tx*4..+3} (zero Bs bank conflicts).
// CONCAT: A is the virtual concat [A0(.,256) | A1(.,32)] (float4 never
// straddles the boundary since OBSD % 4 == 0).
// MODE 0: C = relu(A*W + bias)
// MODE 1: C = A*W + bias
// MODE 2: distance-argmin epilogue replicating the reference's fp32 rounding:
//         d_j = fl( fl(xn_row - 2*s_j) + ecn_j )   [bias == ecn, xn == |x|^2]
//         This reproduces the reference's quantization-induced ties, resolved
//         to the smallest index via the packed atomicMin key.
// MODE 3: MODE 1 + fused sum((C - ref)^2) into lacc (recon loss)
// ---------------------------------------------------------------------------
template <int MODE, int K, int N, bool CONCAT>
__global__ __launch_bounds__(256, 2)
void gemm128(const float* __restrict__ A, const float* __restrict__ A1,
             const float* __restrict__ W,
             const float* __restrict__ bias, float* __restrict__ C,
             unsigned long long* __restrict__ amin,
             const float* __restrict__ xn,
             const float* __restrict__ lref, double* __restrict__ lacc) {
    __shared__ float As[2][16][128];
    __shared__ float Bs[2][16][128];

    const int tid = threadIdx.x;
    const int tx = tid & 15;          // 0..15 -> column group
    const int ty = tid >> 4;          // 0..15 -> row group
    const int rowBase = blockIdx.y * 128;
    const int colBase = blockIdx.x * 128;

    // A loader: 4 threads per row, rows tid>>2 and (tid>>2)+64
    const int a_r = tid >> 2;
    const int a_k = (tid & 3) * 4;
    // B loader: 32 threads per k-row, k-rows tid>>5 and (tid>>5)+8
    const int b_r = tid >> 5;
    const int b_c = (tid & 31) * 4;

    // Non-concat A pointers (stride K)
    const float* Aptr  = A + (size_t)(rowBase + a_r) * K + a_k;
    const float* Aptr2 = Aptr + (size_t)64 * K;
    // Concat row bases (strides OBSD / ACTD)
    const float* Ao1 = CONCAT ? A  + (size_t)(rowBase + a_r) * OBSD : nullptr;
    const float* Ao2 = CONCAT ? Ao1 + (size_t)64 * OBSD : nullptr;
    const float* Aa1 = CONCAT ? A1 + (size_t)(rowBase + a_r) * ACTD : nullptr;
    const float* Aa2 = CONCAT ? Aa1 + (size_t)64 * ACTD : nullptr;
    int cA = a_k;  // current A column for CONCAT path

    const float* Wptr = W + (size_t)b_r * N + colBase + b_c;

    float acc[8][8];
    #pragma unroll
    for (int i = 0; i < 8; i++)
        #pragma unroll
        for (int j = 0; j < 8; j++) acc[i][j] = 0.f;

    constexpr int nIter = K / 16;

    // prologue: load tile 0 into regs, stage to smem buffer 0
    float4 av1, av2, bv1, bv2;
    if (CONCAT) {
        av1 = (cA < OBSD) ? *(const float4*)(Ao1 + cA) : *(const float4*)(Aa1 + (cA - OBSD));
        av2 = (cA < OBSD) ? *(const float4*)(Ao2 + cA) : *(const float4*)(Aa2 + (cA - OBSD));
    } else {
        av1 = *(const float4*)Aptr;
        av2 = *(const float4*)Aptr2;
    }
    bv1 = *(const float4*)Wptr;
    bv2 = *(const float4*)(Wptr + (size_t)8 * N);

    As[0][a_k + 0][a_r]      = av1.x; As[0][a_k + 1][a_r]      = av1.y;
    As[0][a_k + 2][a_r]      = av1.z; As[0][a_k + 3][a_r]      = av1.w;
    As[0][a_k + 0][a_r + 64] = av2.x; As[0][a_k + 1][a_r + 64] = av2.y;
    As[0][a_k + 2][a_r + 64] = av2.z; As[0][a_k + 3][a_r + 64] = av2.w;
    *(float4*)&Bs[0][b_r][b_c]     = bv1;
    *(float4*)&Bs[0][b_r + 8][b_c] = bv2;
    __syncthreads();

    for (int it = 0; it < nIter; it++) {
        const int cur = it & 1;
        const bool more = (it + 1) < nIter;

        // prefetch tile it+1 into registers (latency overlapped with compute)
        if (more) {
            if (CONCAT) {
                cA += 16;
                av1 = (cA < OBSD) ? *(const float4*)(Ao1 + cA)
                                  : *(const float4*)(Aa1 + (cA - OBSD));
                av2 = (cA < OBSD) ? *(const float4*)(Ao2 + cA)
                                  : *(const float4*)(Aa2 + (cA - OBSD));
            } else {
                Aptr += 16; Aptr2 += 16;
                av1 = *(const float4*)Aptr;
                av2 = *(const float4*)Aptr2;
            }
            Wptr += (size_t)16 * N;
            bv1 = *(const float4*)Wptr;
            bv2 = *(const float4*)(Wptr + (size_t)8 * N);
        }

        #pragma unroll
        for (int k = 0; k < 16; k++) {
            float a[8], b[8];
            *(float4*)(a)     = *(const float4*)&As[cur][k][ty * 4];
            *(float4*)(a + 4) = *(const float4*)&As[cur][k][64 + ty * 4];
            *(float4*)(b)     = *(const float4*)&Bs[cur][k][tx * 4];
            *(float4*)(b + 4) = *(const float4*)&Bs[cur][k][64 + tx * 4];
            #pragma unroll
            for (int i = 0; i < 8; i++)
                #pragma unroll
                for (int j = 0; j < 8; j++)
                    acc[i][j] = fmaf(a[i], b[j], acc[i][j]);
        }

        if (more) {
            const int nxt = cur ^ 1;
            As[nxt][a_k + 0][a_r]      = av1.x; As[nxt][a_k + 1][a_r]      = av1.y;
            As[nxt][a_k + 2][a_r]      = av1.z; As[nxt][a_k + 3][a_r]      = av1.w;
            As[nxt][a_k + 0][a_r + 64] = av2.x; As[nxt][a_k + 1][a_r + 64] = av2.y;
            As[nxt][a_k + 2][a_r + 64] = av2.z; As[nxt][a_k + 3][a_r + 64] = av2.w;
            *(float4*)&Bs[nxt][b_r][b_c]     = bv1;
            *(float4*)&Bs[nxt][b_r + 8][b_c] = bv2;
            __syncthreads();
        }
    }

    // local row index for accumulator slot i
    // i<4 -> ty*4 + i ; i>=4 -> 64 + ty*4 + (i-4)
    if (MODE == 2) {
        const int cbA = colBase + tx * 4;
        const int cbB = colBase + 64 + tx * 4;
        float ev[8];
        *(float4*)(ev)     = *(const float4*)(bias + cbA);
        *(float4*)(ev + 4) = *(const float4*)(bias + cbB);
        #pragma unroll
        for (int i = 0; i < 8; i++) {
            const int row = (i < 4) ? (ty * 4 + i) : (64 + ty * 4 + (i - 4));
            const float xr = xn[rowBase + row];
            unsigned long long best = ~0ULL;
            #pragma unroll
            for (int j = 0; j < 8; j++) {
                // replicate reference rounding: fl(fl(xn - 2s) + en)
                float t = fmaf(-2.0f, acc[i][j], xr);
                float d = t + ev[j];
                const int col = (j < 4) ? (cbA + j) : (cbB + (j - 4));
                unsigned long long p =
                    ((unsigned long long)sortkey(d) << 32) | (unsigned)col;
                best = p < best ? p : best;
            }
            #pragma unroll
            for (int o = 8; o > 0; o >>= 1) {
                unsigned long long v = __shfl_xor_sync(0xffffffffu, best, o);
                best = v < best ? v : best;
            }
            if (tx == 0)
                atomicMin(&amin[rowBase + row], best);
        }
    } else {
        const int cbA = colBase + tx * 4;
        const int cbB = colBase + 64 + tx * 4;
        float bs[8];
        *(float4*)(bs)     = *(const float4*)(bias + cbA);
        *(float4*)(bs + 4) = *(const float4*)(bias + cbB);
        float lsum = 0.f;
        #pragma unroll
        for (int i = 0; i < 8; i++) {
            const int row = (i < 4) ? (ty * 4 + i) : (64 + ty * 4 + (i - 4));
            float* Crow = C + (size_t)(rowBase + row) * N;
            float4 o1, o2;
            float v0 = acc[i][0] + bs[0], v1 = acc[i][1] + bs[1];
            float v2 = acc[i][2] + bs[2], v3 = acc[i][3] + bs[3];
            float v4 = acc[i][4] + bs[4], v5 = acc[i][5] + bs[5];
            float v6 = acc[i][6] + bs[6], v7 = acc[i][7] + bs[7];
            if (MODE == 0) {
                v0 = fmaxf(v0, 0.f); v1 = fmaxf(v1, 0.f);
                v2 = fmaxf(v2, 0.f); v3 = fmaxf(v3, 0.f);
                v4 = fmaxf(v4, 0.f); v5 = fmaxf(v5, 0.f);
                v6 = fmaxf(v6, 0.f); v7 = fmaxf(v7, 0.f);
            }
            o1.x = v0; o1.y = v1; o1.z = v2; o1.w = v3;
            o2.x = v4; o2.y = v5; o2.z = v6; o2.w = v7;
            *(float4*)(Crow + cbA) = o1;
            *(float4*)(Crow + cbB) = o2;
            if (MODE == 3) {
                const float* Rrow = lref + (size_t)(rowBase + row) * N;
                float4 r1 = *(const float4*)(Rrow + cbA);
                float4 r2 = *(const float4*)(Rrow + cbB);
                float d0 = v0 - r1.x, d1 = v1 - r1.y, d2 = v2 - r1.z, d3 = v3 - r1.w;
                float d4 = v4 - r2.x, d5 = v5 - r2.y, d6 = v6 - r2.z, d7 = v7 - r2.w;
                lsum = fmaf(d0, d0, lsum); lsum = fmaf(d1, d1, lsum);
                lsum = fmaf(d2, d2, lsum); lsum = fmaf(d3, d3, lsum);
                lsum = fmaf(d4, d4, lsum); lsum = fmaf(d5, d5, lsum);
                lsum = fmaf(d6, d6, lsum); lsum = fmaf(d7, d7, lsum);
            }
        }
        if (MODE == 3) {
            float s = block_reduce_sum(lsum);
            if (tid == 0) atomicAdd(lacc, (double)s);
        }
    }
}

// ---------------------------------------------------------------------------
// gather quantized rows, emit tokens, accumulate sum((lat - q)^2)
// ---------------------------------------------------------------------------
__global__ void gather_quant(const unsigned long long* __restrict__ amin,
                             const float* __restrict__ emb,
                             const float* __restrict__ lat,
                             float* __restrict__ out_tok,
                             float* __restrict__ out_q,
                             double* __restrict__ acc) {
    int row = blockIdx.x;
    int t = threadIdx.x;  // 256 == LATD
    unsigned idx = (unsigned)(amin[row] & 0xffffffffu);
    float q = emb[(size_t)idx * LATD + t];
    float l = lat[(size_t)row * LATD + t];
    out_q[(size_t)row * LATD + t] = q;
    float d = l - q;
    float s = block_reduce_sum(d * d);
    if (t == 0) {
        out_tok[row] = (float)idx;
        atomicAdd(&acc[0], (double)s);
    }
}

// ---------------------------------------------------------------------------
// scalars: recon_loss, commitment, codebook, total_quant, total
// ---------------------------------------------------------------------------
__global__ void finalize(const double* __restrict__ acc, float* __restrict__ scal) {
    double mq = acc[0] / ((double)NROW * (double)LATD);
    double mr = acc[1] / ((double)NROW * (double)OBSD);
    scal[0] = (float)mr;
    scal[1] = (float)(0.25 * mq);
    scal[2] = (float)mq;
    scal[3] = (float)(1.25 * mq);
    scal[4] = (float)(mr + 1.25 * mq);
}

// ---------------------------------------------------------------------------
extern "C" void kernel_launch(void* const* d_in, const int* in_sizes, int n_in,
                              void* d_out, int out_size) {
    (void)in_sizes; (void)n_in; (void)out_size;
    const float* obs     = (const float*)d_in[0];
    const float* actions = (const float*)d_in[1];
    const float* enc_w1  = (const float*)d_in[2];
    const float* enc_b1  = (const float*)d_in[3];
    const float* enc_w2  = (const float*)d_in[4];
    const float* enc_b2  = (const float*)d_in[5];
    const float* enc_w3  = (const float*)d_in[6];
    const float* enc_b3  = (const float*)d_in[7];
    const float* emb     = (const float*)d_in[8];
    const float* dec_w1  = (const float*)d_in[9];
    const float* dec_b1  = (const float*)d_in[10];
    const float* dec_w2  = (const float*)d_in[11];
    const float* dec_b2  = (const float*)d_in[12];
    const float* dec_w3  = (const float*)d_in[13];
    const float* dec_b3  = (const float*)d_in[14];

    float* S = nullptr;
    cudaGetSymbolAddress((void**)&S, g_scratch);
    float* H1   = S + OFF_H1;
    float* H2   = S + OFF_H2;
    float* EMBT = S + OFF_EMBT;
    float* ECN  = S + OFF_ECN;
    float* XN   = S + OFF_XN;
    unsigned long long* AM = (unsigned long long*)(S + OFF_ARGMIN);
    double* ACC = (double*)(S + OFF_ACC);

    float* out   = (float*)d_out;
    float* recon = out + OUT_RECON;
    float* tok   = out + OUT_TOK;
    float* q     = out + OUT_Q;
    float* lat   = out + OUT_LAT;
    float* scal  = out + OUT_SCAL;

    init_kernel<<<NROW / 256, 256>>>(AM, ACC);
    ecn_kernel<<<KCODE / 8, 256>>>(emb, ECN);
    transpose_emb<<<dim3(KCODE / 32, LATD / 32), dim3(32, 32)>>>(emb, EMBT);

    // encoder (layer 1 reads concat(obs, actions) directly)
    gemm128<0, CIN, HID, true><<<dim3(HID / 128, NROW / 128), 256>>>(
        obs, actions, enc_w1, enc_b1, H1, nullptr, nullptr, nullptr, nullptr);
    gemm128<0, HID, HID, false><<<dim3(HID / 128, NROW / 128), 256>>>(
        H1, nullptr, enc_w2, enc_b2, H2, nullptr, nullptr, nullptr, nullptr);
    gemm128<1, HID, LATD, false><<<dim3(LATD / 128, NROW / 128), 256>>>(
        H2, nullptr, enc_w3, enc_b3, lat, nullptr, nullptr, nullptr, nullptr);

    // quantize: xn then distance-argmin with reference-matching rounding
    row_norms<<<NROW / 8, 256>>>(lat, XN);
    gemm128<2, LATD, KCODE, false><<<dim3(KCODE / 128, NROW / 128), 256>>>(
        lat, nullptr, EMBT, ECN, nullptr, AM, XN, nullptr, nullptr);
    gather_quant<<<NROW, LATD>>>(AM, emb, lat, tok, q, ACC);

    // decoder (layer 1 reads concat(q, actions) directly; STE == q numerically)
    gemm128<0, CIN, HID, true><<<dim3(HID / 128, NROW / 128), 256>>>(
        q, actions, dec_w1, dec_b1, H1, nullptr, nullptr, nullptr, nullptr);
    gemm128<0, HID, HID, false><<<dim3(HID / 128, NROW / 128), 256>>>(
        H1, nullptr, dec_w2, dec_b2, H2, nullptr, nullptr, nullptr, nullptr);
    // final layer: fused recon write + recon-loss accumulation
    gemm128<3, HID, OBSD, false><<<dim3(OBSD / 128, NROW / 128), 256>>>(
        H2, nullptr, dec_w3, dec_b3, recon, nullptr, nullptr, obs, &ACC[1]);

    finalize<<<1, 1>>>(ACC, scal);
}